// round 8
// baseline (speedup 1.0000x reference)
#include <cuda_runtime.h>
#include <cstdint>

// Problem constants
#define BB 4
#define SS 4096
#define DF 1024
#define HH 16
#define HD 64
#define SK 1024          // SS / STRIDE
#define STRIDE 4
#define BQ 64            // q rows per CTA
#define BK 64            // k cols per block
#define NBLK (SK / BK)   // 16
#define NT 256
#define PAD 68           // floats per row (conflict-free for all frag patterns)
#define KSTG 17408       // bytes per 64x68 float stage

// smem layout: Q region (reused as reduction buffers) + 4 stages (K0,K1,V0,V1)
#define SM_Q   0                 // 64*68*4 = 17408
#define SM_ACC 0                 // end-of-kernel: 4mg*32lane*33 floats = 16896
#define SM_RS  16896             // 128 floats = 512 (16896+512 = 17408)
#define SM_S0  17408
#define SM_TOTAL (SM_S0 + 4*KSTG)   // 87040

__device__ __forceinline__ uint32_t smem_u32(const void* p) {
    uint32_t a;
    asm("{ .reg .u64 t; cvta.to.shared.u64 t, %1; cvt.u32.u64 %0, t; }" : "=r"(a) : "l"(p));
    return a;
}

#define CP_ASYNC16(sa, gp) \
    asm volatile("cp.async.cg.shared.global [%0], [%1], 16;" :: "r"(sa), "l"(gp) : "memory")
#define CP_COMMIT() asm volatile("cp.async.commit_group;" ::: "memory")
#define CP_WAIT(N)  asm volatile("cp.async.wait_group %0;" :: "n"(N) : "memory")

// D += A * B  (m16n8k8, tf32 in, f32 out). A row-major, B col-major fragments.
__device__ __forceinline__ void mma_tf32(float c[4], const float a[4], const float b[2]) {
    asm volatile(
        "mma.sync.aligned.m16n8k8.row.col.f32.tf32.tf32.f32 "
        "{%0,%1,%2,%3}, {%4,%5,%6,%7}, {%8,%9}, {%0,%1,%2,%3};"
        : "+f"(c[0]), "+f"(c[1]), "+f"(c[2]), "+f"(c[3])
        : "r"(__float_as_uint(a[0])), "r"(__float_as_uint(a[1])),
          "r"(__float_as_uint(a[2])), "r"(__float_as_uint(a[3])),
          "r"(__float_as_uint(b[0])), "r"(__float_as_uint(b[1])));
}

// round-to-nearest tf32 (unbiased; HW mma truncates otherwise)
__device__ __forceinline__ float tf32_rn(float x) {
    return __uint_as_float((__float_as_uint(x) + 0x1000u) & 0xFFFFE000u);
}

__global__ __launch_bounds__(NT, 2)
void attn_mma_kernel(const float* __restrict__ gq, const float* __restrict__ gk,
                     const float* __restrict__ gv, float* __restrict__ out_a,
                     float* __restrict__ out_w)
{
    extern __shared__ char sm[];
    const uint32_t smb = smem_u32(sm);
    float* qs = (float*)(sm + SM_Q);

    const int tid = threadIdx.x, lane = tid & 31, warp = tid >> 5;
    const int gid = lane >> 2, gc = lane & 3;            // fragment row-group / col
    const int mg = warp >> 1, ng = warp & 1;             // m-group / k-slice
    const int b = blockIdx.z, h = blockIdx.y, q0 = blockIdx.x * BQ;
    const int r0 = mg * 16 + gid;                        // base q-row within CTA

    const float* kbase = gk + (size_t)b * SS * DF + h * HD;
    const float* vbase = gv + (size_t)b * SS * DF + h * HD;

    // per-thread cp.async slice coords (4 chunks per 64-row stage)
    const int lr = tid >> 4;              // rows lr, lr+16, lr+32, lr+48
    const int lc = (tid & 15) << 2;       // float offset within row

    // ---- pre-issue K/V block 0 ----
    {
        #pragma unroll
        for (int i = 0; i < 4; i++) {
            int r = lr + i * 16;
            size_t goff = (size_t)(r * STRIDE) * DF + lc;
            CP_ASYNC16(smb + SM_S0 +            (uint32_t)(r * PAD + lc) * 4, kbase + goff);
            CP_ASYNC16(smb + SM_S0 + 2 * KSTG + (uint32_t)(r * PAD + lc) * 4, vbase + goff);
        }
        CP_COMMIT();
    }

    // ---- stage Q (64 rows): scale by 1/8, pre-round tf32 RN ----
    {
        const float* qb = gq + ((size_t)(b * SS + q0)) * DF + h * HD;
        #pragma unroll
        for (int i = 0; i < 4; i++) {
            int idx = tid + i * NT;          // 0..1023
            int r = idx >> 4, c4 = (idx & 15) << 2;
            float4 x = *(const float4*)&qb[(size_t)r * DF + c4];
            x.x = tf32_rn(x.x * 0.125f); x.y = tf32_rn(x.y * 0.125f);
            x.z = tf32_rn(x.z * 0.125f); x.w = tf32_rn(x.w * 0.125f);
            *(float4*)&qs[r * PAD + c4] = x;
        }
    }
    __syncthreads();

    // ---- Q fragments -> registers (resident for whole kernel) ----
    float Qf[8][4];
    #pragma unroll
    for (int j = 0; j < 8; j++) {
        Qf[j][0] = qs[r0 * PAD + j * 8 + gc];
        Qf[j][1] = qs[(r0 + 8) * PAD + j * 8 + gc];
        Qf[j][2] = qs[r0 * PAD + j * 8 + gc + 4];
        Qf[j][3] = qs[(r0 + 8) * PAD + j * 8 + gc + 4];
    }

    float Acc[8][4];
    #pragma unroll
    for (int t = 0; t < 8; t++) {
        Acc[t][0] = 0.f; Acc[t][1] = 0.f; Acc[t][2] = 0.f; Acc[t][3] = 0.f;
    }
    float rs0 = 0.f, rs1 = 0.f;

    for (int blk = 0; blk < NBLK; blk++) {
        CP_WAIT(0);
        __syncthreads();   // K/V(blk) visible; all warps done reading buf^1

        if (blk + 1 < NBLK) {
            const uint32_t ks_ = smb + SM_S0 + ((blk + 1) & 1) * KSTG;
            const uint32_t vs_ = ks_ + 2 * KSTG;
            #pragma unroll
            for (int i = 0; i < 4; i++) {
                int r = lr + i * 16;
                size_t goff = (size_t)(((blk + 1) * BK + r) * STRIDE) * DF + lc;
                CP_ASYNC16(ks_ + (uint32_t)(r * PAD + lc) * 4, kbase + goff);
                CP_ASYNC16(vs_ + (uint32_t)(r * PAD + lc) * 4, vbase + goff);
            }
            CP_COMMIT();
        }

        const float* kb = (const float*)(sm + SM_S0 + (blk & 1) * KSTG);
        const float* vb = kb + 2 * (KSTG / 4);

        // ---- S = Q * K^T  over this warp's 32-col k-slice ----
        float S[4][4];
        #pragma unroll
        for (int t = 0; t < 4; t++) {
            S[t][0] = 0.f; S[t][1] = 0.f; S[t][2] = 0.f; S[t][3] = 0.f;
        }
        #pragma unroll
        for (int j = 0; j < 8; j++) {
            #pragma unroll
            for (int t = 0; t < 4; t++) {
                float bf[2];
                bf[0] = tf32_rn(kb[(ng * 32 + t * 8 + gid) * PAD + j * 8 + gc]);
                bf[1] = tf32_rn(kb[(ng * 32 + t * 8 + gid) * PAD + j * 8 + gc + 4]);
                mma_tf32(S[t], Qf[j], bf);
            }
        }

        // ---- exp, row-sum, unnormalized w -> gmem; S becomes P (RN'd) ----
        float* wr0 = out_w + (((size_t)(b * HH + h)) * SS + q0 + r0) * SK
                   + blk * BK + ng * 32;
        float* wr1 = wr0 + (size_t)8 * SK;
        #pragma unroll
        for (int t = 0; t < 4; t++) {
            float p0 = __expf(S[t][0]), p1 = __expf(S[t][1]);
            float p2 = __expf(S[t][2]), p3 = __expf(S[t][3]);
            rs0 += p0 + p1;
            rs1 += p2 + p3;
            int col = t * 8 + 2 * gc;
            *(float2*)&wr0[col] = make_float2(p0, p1);
            *(float2*)&wr1[col] = make_float2(p2, p3);
            S[t][0] = tf32_rn(p0); S[t][1] = tf32_rn(p1);
            S[t][2] = tf32_rn(p2); S[t][3] = tf32_rn(p3);
        }

        // ---- Acc += P * V  (partial over this k-slice, full d=64) ----
        // A-frag slots {c0,c2,c1,c3}; B rows 2gc, 2gc+1 within slice
        #pragma unroll
        for (int j = 0; j < 4; j++) {
            float ap[4];
            ap[0] = S[j][0]; ap[1] = S[j][2];
            ap[2] = S[j][1]; ap[3] = S[j][3];
            #pragma unroll
            for (int t = 0; t < 8; t++) {
                float bf[2];
                bf[0] = tf32_rn(vb[(ng * 32 + j * 8 + 2 * gc)     * PAD + t * 8 + gid]);
                bf[1] = tf32_rn(vb[(ng * 32 + j * 8 + 2 * gc + 1) * PAD + t * 8 + gid]);
                mma_tf32(Acc[t], ap, bf);
            }
        }
    }

    // ---- combine k-slice partials: row sums + Acc across ng pairs ----
    rs0 += __shfl_xor_sync(0xFFFFFFFFu, rs0, 1);
    rs0 += __shfl_xor_sync(0xFFFFFFFFu, rs0, 2);
    rs1 += __shfl_xor_sync(0xFFFFFFFFu, rs1, 1);
    rs1 += __shfl_xor_sync(0xFFFFFFFFu, rs1, 2);

    __syncthreads();   // mainloop done; SM_Q region reusable
    float* accbuf = (float*)(sm + SM_ACC);   // stride 33, SCALAR access (4B aligned)
    float* rsb    = (float*)(sm + SM_RS);
    if (gc == 0) {
        rsb[ng * 64 + r0]     = rs0;
        rsb[ng * 64 + r0 + 8] = rs1;
    }
    if (ng == 1) {
        float* ab = accbuf + (mg * 32 + lane) * 33;   // bank = lane -> conflict-free
        #pragma unroll
        for (int t = 0; t < 8; t++) {
            ab[t * 4 + 0] = Acc[t][0];
            ab[t * 4 + 1] = Acc[t][1];
            ab[t * 4 + 2] = Acc[t][2];
            ab[t * 4 + 3] = Acc[t][3];
        }
    }
    __syncthreads();
    if (tid < 64) rsb[tid] = 1.0f / (rsb[tid] + rsb[64 + tid]);
    __syncthreads();

    // ---- a: ng=0 warps add partner partial, normalize, store ----
    if (ng == 0) {
        const float inv0 = rsb[r0], inv1 = rsb[r0 + 8];
        const float* pb = accbuf + (mg * 32 + lane) * 33;
        float* ar0 = out_a + ((size_t)(b * SS + q0 + r0)) * DF + h * HD;
        float* ar1 = ar0 + (size_t)8 * DF;
        #pragma unroll
        for (int t = 0; t < 8; t++) {
            float o0 = pb[t * 4 + 0], o1 = pb[t * 4 + 1];
            float o2 = pb[t * 4 + 2], o3 = pb[t * 4 + 3];
            int col = t * 8 + 2 * gc;
            *(float2*)&ar0[col] = make_float2((Acc[t][0] + o0) * inv0,
                                              (Acc[t][1] + o1) * inv0);
            *(float2*)&ar1[col] = make_float2((Acc[t][2] + o2) * inv1,
                                              (Acc[t][3] + o3) * inv1);
        }
    }

    // ---- w: rescale in place (slab is L2-resident: 256KB * 296 CTAs = 74MB) ----
    {
        float* wslab = out_w + (((size_t)(b * HH + h)) * SS + q0) * SK;
        #pragma unroll 4
        for (int idx = tid; idx < BQ * 256; idx += NT) {
            int r = idx >> 8, c4 = (idx & 255) << 2;
            float il = rsb[r];
            float4 t = *(float4*)&wslab[(size_t)r * SK + c4];
            t.x *= il; t.y *= il; t.z *= il; t.w *= il;
            *(float4*)&wslab[(size_t)r * SK + c4] = t;
        }
    }
}

extern "C" void kernel_launch(void* const* d_in, const int* in_sizes, int n_in,
                              void* d_out, int out_size)
{
    (void)in_sizes; (void)n_in; (void)out_size;
    const float* q = (const float*)d_in[0];
    const float* k = (const float*)d_in[1];
    const float* v = (const float*)d_in[2];

    float* out_a = (float*)d_out;
    float* out_w = out_a + (size_t)BB * SS * DF;  // w follows a

    cudaFuncSetAttribute(attn_mma_kernel,
                         cudaFuncAttributeMaxDynamicSharedMemorySize, SM_TOTAL);

    dim3 grid(SS / BQ, HH, BB);   // (64, 16, 4) = 4096 CTAs
    attn_mma_kernel<<<grid, NT, SM_TOTAL>>>(q, k, v, out_a, out_w);
}